// round 1
// baseline (speedup 1.0000x reference)
#include <cuda_runtime.h>

// RAPiD detection-head decode.
// raw:     (64, 18, 128, 128) fp32, channel c = a*6 + ch
// anchors: (3, 2) fp32
// img_h, img_w: int32 scalars (device)
// out:     (64, 3*128*128, 6) fp32, layout [b][a][h][w][ch]

#define NB 64
#define NA 3
#define NH 128
#define NW 128
#define PLANE (NH * NW)           // 16384
#define ANGLE_RANGE 360.0f

__device__ __forceinline__ float sigmoidf_fast(float x) {
    return 1.0f / (1.0f + __expf(-x));
}

__global__ void __launch_bounds__(256) rapid_decode_kernel(
    const float* __restrict__ raw,
    const float* __restrict__ anchors,
    const int*   __restrict__ img_h_p,
    const int*   __restrict__ img_w_p,
    float*       __restrict__ out)
{
    // One thread handles 4 consecutive w-pixels.
    // total threads = NB*NA*NH*(NW/4) = 64*3*128*32 = 786432
    int t = blockIdx.x * blockDim.x + threadIdx.x;

    int w4 = t & 31;               // which group of 4 along w (NW/4 = 32)
    int h  = (t >> 5) & 127;       // NH = 128
    int a  = (t >> 12) % NA;       // 32*128 = 4096
    int b  = t / (32 * 128 * NA);  // 12288

    const float sx = (float)img_w_p[0] / (float)NW;
    const float sy = (float)img_h_p[0] / (float)NH;
    const float aw = anchors[a * 2 + 0];
    const float ah = anchors[a * 2 + 1];

    const int w0 = w4 * 4;
    const float* base = raw + (size_t)((b * 18 + a * 6) * PLANE + h * NW + w0);

    // 6 channel planes, 64KB apart; each load coalesced across the warp.
    float4 r0 = *(const float4*)(base + 0 * PLANE);
    float4 r1 = *(const float4*)(base + 1 * PLANE);
    float4 r2 = *(const float4*)(base + 2 * PLANE);
    float4 r3 = *(const float4*)(base + 3 * PLANE);
    float4 r4 = *(const float4*)(base + 4 * PLANE);
    float4 r5 = *(const float4*)(base + 5 * PLANE);

    float v0[4] = {r0.x, r0.y, r0.z, r0.w};
    float v1[4] = {r1.x, r1.y, r1.z, r1.w};
    float v2[4] = {r2.x, r2.y, r2.z, r2.w};
    float v3[4] = {r3.x, r3.y, r3.z, r3.w};
    float v4[4] = {r4.x, r4.y, r4.z, r4.w};
    float v5[4] = {r5.x, r5.y, r5.z, r5.w};

    float o[24];
    #pragma unroll
    for (int i = 0; i < 4; i++) {
        float px = (sigmoidf_fast(v0[i]) + (float)(w0 + i)) * sx;
        float py = (sigmoidf_fast(v1[i]) + (float)h)        * sy;
        float pw = __expf(v2[i]) * aw;
        float ph = __expf(v3[i]) * ah;
        float pa = sigmoidf_fast(v4[i]) * ANGLE_RANGE - ANGLE_RANGE * 0.5f;
        float pc = sigmoidf_fast(v5[i]);
        o[i * 6 + 0] = px;
        o[i * 6 + 1] = py;
        o[i * 6 + 2] = pw;
        o[i * 6 + 3] = ph;
        o[i * 6 + 4] = pa;
        o[i * 6 + 5] = pc;
    }

    // Output: 4 pixels * 6 floats = 96 contiguous bytes, 16B-aligned.
    float4* op = (float4*)(out + (size_t)((b * NA + a) * PLANE + h * NW + w0) * 6);
    #pragma unroll
    for (int j = 0; j < 6; j++) {
        op[j] = make_float4(o[j * 4 + 0], o[j * 4 + 1], o[j * 4 + 2], o[j * 4 + 3]);
    }
}

extern "C" void kernel_launch(void* const* d_in, const int* in_sizes, int n_in,
                              void* d_out, int out_size)
{
    const float* raw     = (const float*)d_in[0];
    const float* anchors = (const float*)d_in[1];
    const int*   img_h   = (const int*)d_in[2];
    const int*   img_w   = (const int*)d_in[3];
    float* out = (float*)d_out;

    const int total_threads = NB * NA * NH * (NW / 4); // 786432
    const int block = 256;
    const int grid = total_threads / block;            // 3072
    rapid_decode_kernel<<<grid, block>>>(raw, anchors, img_h, img_w, out);
}

// round 2
// speedup vs baseline: 1.1877x; 1.1877x over previous
#include <cuda_runtime.h>

// RAPiD detection-head decode, smem-staged coalesced stores.
// raw:     (64, 18, 128, 128) fp32, channel c = a*6 + ch
// anchors: (3, 2) fp32
// img_h, img_w: int32 scalars (device)
// out:     (64, 3*128*128, 6) fp32, layout [b][a][h][w][ch]

#define NB 64
#define NA 3
#define NH 128
#define NW 128
#define PLANE (NH * NW)           // 16384
#define ANGLE_RANGE 360.0f
#define TPB 256
#define PAD_STRIDE 25             // floats per thread in smem (odd -> conflict-free STS)

__device__ __forceinline__ float sigmoidf_fast(float x) {
    return 1.0f / (1.0f + __expf(-x));
}

__global__ void __launch_bounds__(TPB) rapid_decode_kernel(
    const float* __restrict__ raw,
    const float* __restrict__ anchors,
    const int*   __restrict__ img_h_p,
    const int*   __restrict__ img_w_p,
    float*       __restrict__ out)
{
    __shared__ float sh[TPB * PAD_STRIDE];   // 25.6 KB

    const int tid = threadIdx.x;
    const int t = blockIdx.x * TPB + tid;

    // thread -> 4 consecutive w-pixels
    const int w4 = t & 31;                 // NW/4 = 32
    const int h  = (t >> 5) & 127;         // NH = 128
    const int a  = (t >> 12) % NA;
    const int b  = t / (32 * 128 * NA);

    const float sx = (float)img_w_p[0] / (float)NW;
    const float sy = (float)img_h_p[0] / (float)NH;
    const float aw = anchors[a * 2 + 0];
    const float ah = anchors[a * 2 + 1];

    const int w0 = w4 * 4;
    const float* base = raw + (size_t)((b * 18 + a * 6) * PLANE + h * NW + w0);

    // 6 channel planes, 64KB apart; each LDG.128 fully coalesced (16B lane stride).
    float4 r0 = *(const float4*)(base + 0 * PLANE);
    float4 r1 = *(const float4*)(base + 1 * PLANE);
    float4 r2 = *(const float4*)(base + 2 * PLANE);
    float4 r3 = *(const float4*)(base + 3 * PLANE);
    float4 r4 = *(const float4*)(base + 4 * PLANE);
    float4 r5 = *(const float4*)(base + 5 * PLANE);

    float v0[4] = {r0.x, r0.y, r0.z, r0.w};
    float v1[4] = {r1.x, r1.y, r1.z, r1.w};
    float v2[4] = {r2.x, r2.y, r2.z, r2.w};
    float v3[4] = {r3.x, r3.y, r3.z, r3.w};
    float v4[4] = {r4.x, r4.y, r4.z, r4.w};
    float v5[4] = {r5.x, r5.y, r5.z, r5.w};

    // Stage this thread's 24 output floats (4 pixels x 6 channels) in smem,
    // padded stride 25 -> scalar STS conflict-free across the warp.
    float* mysh = sh + tid * PAD_STRIDE;
    #pragma unroll
    for (int i = 0; i < 4; i++) {
        float px = (sigmoidf_fast(v0[i]) + (float)(w0 + i)) * sx;
        float py = (sigmoidf_fast(v1[i]) + (float)h)        * sy;
        float pw = __expf(v2[i]) * aw;
        float ph = __expf(v3[i]) * ah;
        float pa = sigmoidf_fast(v4[i]) * ANGLE_RANGE - ANGLE_RANGE * 0.5f;
        float pc = sigmoidf_fast(v5[i]);
        mysh[i * 6 + 0] = px;
        mysh[i * 6 + 1] = py;
        mysh[i * 6 + 2] = pw;
        mysh[i * 6 + 3] = ph;
        mysh[i * 6 + 4] = pa;
        mysh[i * 6 + 5] = pc;
    }

    __syncwarp();

    // Warp-local copy-out: warp's 32 threads produced 768 floats that form one
    // contiguous 3072B region of the output. Gather from padded smem, store as
    // fully coalesced STG.128 (consecutive lanes -> consecutive float4s).
    const int lane = tid & 31;
    const int warp = tid >> 5;
    const float* wsh = sh + (warp * 32) * PAD_STRIDE;

    // Output base for this warp: first pixel handled by lane 0 of this warp.
    const size_t warp_pix0 = (size_t)(blockIdx.x * TPB + warp * 32) * 4;
    float4* op = (float4*)(out + warp_pix0 * 6);

    #pragma unroll
    for (int k = 0; k < 6; k++) {
        int g = lane + 32 * k;     // float4 index within warp tile (0..191)
        int q = g * 4;             // float offset within warp tile
        int row = q / 24;          // producing thread (0..31); q%24 in {0,4,..,20}
        int col = q - row * 24;    // never crosses a thread row for a float4
        const float* s = wsh + row * PAD_STRIDE + col;
        float4 v = make_float4(s[0], s[1], s[2], s[3]);
        op[g] = v;
    }
}

extern "C" void kernel_launch(void* const* d_in, const int* in_sizes, int n_in,
                              void* d_out, int out_size)
{
    const float* raw     = (const float*)d_in[0];
    const float* anchors = (const float*)d_in[1];
    const int*   img_h   = (const int*)d_in[2];
    const int*   img_w   = (const int*)d_in[3];
    float* out = (float*)d_out;

    const int total_threads = NB * NA * NH * (NW / 4); // 786432
    const int grid = total_threads / TPB;              // 3072
    rapid_decode_kernel<<<grid, TPB>>>(raw, anchors, img_h, img_w, out);
}